// round 13
// baseline (speedup 1.0000x reference)
#include <cuda_runtime.h>
#include <cstdint>

// Problem constants
#define T_STEPS 1024
#define BATCH   16
#define NHEADS  12
#define HD      64
#define NG      4
#define NCELLS  (BATCH * NHEADS)          // 192
#define CELLSTR (HD * NG)                 // 256 floats per (t,b,n)
#define TSTRIDE (NCELLS * CELLSTR)        // 49152 floats per timestep of Wx
#define OROW    ((size_t)NCELLS * HD)     // 12288 floats per timestep of out
#define PF      2                         // Wx prefetch distance (timesteps)

typedef unsigned long long ull;

__device__ __forceinline__ ull pk2(float lo, float hi) {
    ull r;
    asm("mov.b64 %0, {%1, %2};" : "=l"(r) : "r"(__float_as_uint(lo)), "r"(__float_as_uint(hi)));
    return r;
}
__device__ __forceinline__ void upk2(ull v, float& lo, float& hi) {
    unsigned a, b2;
    asm("mov.b64 {%0, %1}, %2;" : "=r"(a), "=r"(b2) : "l"(v));
    lo = __uint_as_float(a);
    hi = __uint_as_float(b2);
}
__device__ __forceinline__ void ffma2(ull& acc, ull a, ull b) {
    asm("fma.rn.f32x2 %0, %1, %2, %0;" : "+l"(acc) : "l"(a), "l"(b));
}
__device__ __forceinline__ ull fadd2(ull a, ull b) {
    ull r;
    asm("add.rn.f32x2 %0, %1, %2;" : "=l"(r) : "l"(a), "l"(b));
    return r;
}
__device__ __forceinline__ ull fmul2(ull a, ull b) {
    ull r;
    asm("mul.rn.f32x2 %0, %1, %2;" : "=l"(r) : "l"(a), "l"(b));
    return r;
}
__device__ __forceinline__ float frcp(float x) {
    float r;
    asm("rcp.approx.f32 %0, %1;" : "=f"(r) : "f"(x));
    return r;
}
__device__ __forceinline__ float fex2(float x) {
    float r;
    asm("ex2.approx.f32 %0, %1;" : "=f"(r) : "f"(x));
    return r;
}

// Scales folded into R/bias so the activation core is gate-uniform:
//   r = rcp(1 + ex2(s));  a = fma(k, r, m)
//   sigmoid (g in {0,1,3}): s = -log2(e)*x   -> a = r        (k=1,  m=0)
//   tanh    (g == 2):       s = 2*log2(e)*x  -> a = 1 - 2r   (k=-2, m=1)
#define L2E 1.4426950408889634f

// One 128-thread CTA processes TWO cells of the SAME head: (b0, n) and (b0+8, n).
// R[n,g,o,:] is batch-independent -> both cells share this thread's register R.
__global__ void __launch_bounds__(128, 1)
flashrnn_lstm_kernel(const float* __restrict__ Wx,
                     const float* __restrict__ S0,
                     const float* __restrict__ R,
                     const float* __restrict__ bias,
                     float* __restrict__ out)
{
    const int blk = blockIdx.x;           // 0..95
    const int n  = blk % NHEADS;
    const int b0 = blk / NHEADS;          // 0..7
    const int tid  = threadIdx.x;         // 0..127
    const int warp = tid >> 5;            // 0..3
    const int lane = tid & 31;
    const int g    = lane >> 3;           // gate 0..3 (i,f,z,o)
    const int oA   = (warp << 3) | (lane & 7);  // first owned output (0..31)
    const int oB   = oA + 32;                   // second owned output (32..63)

    __shared__ __align__(16) float sh_h[2][2][HD];  // [cell][pingpong][o]

    // Per-gate activation constants (branch-free core)
    const float sg = (g == 2) ? (2.0f * L2E) : (-L2E);
    const float kg = (g == 2) ? -2.0f : 1.0f;
    const float mg = (g == 2) ?  1.0f : 0.0f;

    // ---- R rows for both output slots, pre-scaled by sg, packed f32x2 ----
    // Shared by BOTH cells (R has no batch dimension).
    ull RpA[32], RpB[32];
    {
        const ull sg2 = pk2(sg, sg);
        const float4* rA = reinterpret_cast<const float4*>(
            R + (((size_t)n * NG + g) * HD + oA) * HD);
        const float4* rB = reinterpret_cast<const float4*>(
            R + (((size_t)n * NG + g) * HD + oB) * HD);
#pragma unroll
        for (int k = 0; k < 16; ++k) {
            float4 vA = rA[k];
            float4 vB = rB[k];
            RpA[2 * k]     = fmul2(pk2(vA.x, vA.y), sg2);
            RpA[2 * k + 1] = fmul2(pk2(vA.z, vA.w), sg2);
            RpB[2 * k]     = fmul2(pk2(vB.x, vB.y), sg2);
            RpB[2 * k + 1] = fmul2(pk2(vB.z, vB.w), sg2);
        }
    }
    const float bvsA = bias[((size_t)n * NG + g) * HD + oA] * sg;
    const float bvsB = bias[((size_t)n * NG + g) * HD + oB] * sg;

    // ---- Cell indices ----
    const size_t bn0 = (size_t)b0 * NHEADS + n;
    const size_t bn1 = (size_t)(b0 + 8) * NHEADS + n;

    // ---- Initial states (c replicated x4 over g-lanes per output) ----
    float cA0 = S0[(size_t)NCELLS * HD + bn0 * HD + oA];
    float cB0 = S0[(size_t)NCELLS * HD + bn0 * HD + oB];
    float cA1 = S0[(size_t)NCELLS * HD + bn1 * HD + oA];
    float cB1 = S0[(size_t)NCELLS * HD + bn1 * HD + oB];

    float* out_h = out;                                 // [1025][192][64]
    float* out_c = out + (size_t)(T_STEPS + 1) * OROW;  // second state plane

    if (g == 0) {
        const float hA0 = S0[bn0 * HD + oA], hB0 = S0[bn0 * HD + oB];
        const float hA1 = S0[bn1 * HD + oA], hB1 = S0[bn1 * HD + oB];
        sh_h[0][0][oA] = hA0;  sh_h[0][0][oB] = hB0;
        sh_h[1][0][oA] = hA1;  sh_h[1][0][oB] = hB1;
        out_h[bn0 * HD + oA] = hA0;  out_h[bn0 * HD + oB] = hB0;   // t=0 h
        out_h[bn1 * HD + oA] = hA1;  out_h[bn1 * HD + oB] = hB1;
    } else if (g == 1) {
        out_c[bn0 * HD + oA] = cA0;  out_c[bn0 * HD + oB] = cB0;   // t=0 c
        out_c[bn1 * HD + oA] = cA1;  out_c[bn1 * HD + oB] = cB1;
    }

    // ---- Wx stream pointers (slot B = +32*NG floats) ----
    const float* wx0 = Wx + bn0 * CELLSTR + (size_t)oA * NG + g;
    const float* wx1 = Wx + bn1 * CELLSTR + (size_t)oA * NG + g;

    __syncthreads();

    float xA0[PF], xB0[PF], xA1[PF], xB1[PF];
#pragma unroll
    for (int j = 0; j < PF; ++j) {
        xA0[j] = __ldcs(wx0 + (size_t)j * TSTRIDE);
        xB0[j] = __ldcs(wx0 + (size_t)j * TSTRIDE + 32 * NG);
        xA1[j] = __ldcs(wx1 + (size_t)j * TSTRIDE);
        xB1[j] = __ldcs(wx1 + (size_t)j * TSTRIDE + 32 * NG);
    }

    int buf = 0;
    float* oh0 = out_h + OROW + bn0 * HD + oA;   // t=1 row; slot B = +32
    float* oc0 = out_c + OROW + bn0 * HD + oA;
    float* oh1 = out_h + OROW + bn1 * HD + oA;
    float* oc1 = out_c + OROW + bn1 * HD + oA;

    for (int t0 = 0; t0 < T_STEPS; t0 += PF) {
        float yA0[PF], yB0[PF], yA1[PF], yB1[PF];
        const bool more = (t0 + PF) < T_STEPS;
#pragma unroll
        for (int j = 0; j < PF; ++j) {
            const float* p0 = wx0 + (size_t)(t0 + PF + j) * TSTRIDE;
            const float* p1 = wx1 + (size_t)(t0 + PF + j) * TSTRIDE;
            yA0[j] = more ? __ldcs(p0) : 0.0f;
            yB0[j] = more ? __ldcs(p0 + 32 * NG) : 0.0f;
            yA1[j] = more ? __ldcs(p1) : 0.0f;
            yB1[j] = more ? __ldcs(p1 + 32 * NG) : 0.0f;
        }

#pragma unroll
        for (int j = 0; j < PF; ++j) {
            // ---- four pre-activation dots (2 outputs x 2 cells), shared R ----
            ull aA0_0 = pk2(fmaf(xA0[j], sg, bvsA), 0.0f), aA0_1 = 0ULL;
            ull aB0_0 = pk2(fmaf(xB0[j], sg, bvsB), 0.0f), aB0_1 = 0ULL;
            ull aA1_0 = pk2(fmaf(xA1[j], sg, bvsA), 0.0f), aA1_1 = 0ULL;
            ull aB1_0 = pk2(fmaf(xB1[j], sg, bvsB), 0.0f), aB1_1 = 0ULL;

            const ulonglong2* hb0 = reinterpret_cast<const ulonglong2*>(sh_h[0][buf]);
            const ulonglong2* hb1 = reinterpret_cast<const ulonglong2*>(sh_h[1][buf]);
#pragma unroll
            for (int k = 0; k < 16; ++k) {           // 2x LDS.128 -> 8 FFMA2
                ulonglong2 t20 = hb0[k];
                ulonglong2 t21 = hb1[k];
                ffma2(aA0_0, RpA[2 * k],     t20.x);
                ffma2(aA0_1, RpA[2 * k + 1], t20.y);
                ffma2(aB0_0, RpB[2 * k],     t20.x);
                ffma2(aB0_1, RpB[2 * k + 1], t20.y);
                ffma2(aA1_0, RpA[2 * k],     t21.x);
                ffma2(aA1_1, RpA[2 * k + 1], t21.y);
                ffma2(aB1_0, RpB[2 * k],     t21.x);
                ffma2(aB1_1, RpB[2 * k + 1], t21.y);
            }
            float lo, hi;
            ull s;
            s = fadd2(aA0_0, aA0_1); upk2(s, lo, hi); const float sA0 = lo + hi;
            s = fadd2(aB0_0, aB0_1); upk2(s, lo, hi); const float sB0 = lo + hi;
            s = fadd2(aA1_0, aA1_1); upk2(s, lo, hi); const float sA1 = lo + hi;
            s = fadd2(aB1_0, aB1_1); upk2(s, lo, hi); const float sB1 = lo + hi;

            // ---- branch-free activations (4 independent MUFU chains) ----
            const float aA0 = fmaf(kg, frcp(1.0f + fex2(sA0)), mg);
            const float aB0 = fmaf(kg, frcp(1.0f + fex2(sB0)), mg);
            const float aA1 = fmaf(kg, frcp(1.0f + fex2(sA1)), mg);
            const float aB1 = fmaf(kg, frcp(1.0f + fex2(sB1)), mg);

            const bool gb0 = (g & 1);
            const bool gb1 = (g & 2);

            // ---- per-slot: gather gates via 3 parallel shuffles, update c/h ----
            float hA0v, hB0v, hA1v, hB1v;
#define SLOT_UPDATE(aV, cV, hOut)                                              \
            {                                                                  \
                const float a1 = __shfl_xor_sync(0xffffffffu, aV, 8);          \
                const float a2 = __shfl_xor_sync(0xffffffffu, aV, 16);         \
                const float a3 = __shfl_xor_sync(0xffffffffu, aV, 24);         \
                const float t0s = gb0 ? a1 : aV;                               \
                const float t1s = gb0 ? a3 : a2;                               \
                const float u0s = gb0 ? aV : a1;                               \
                const float u1s = gb0 ? a2 : a3;                               \
                const float prod = t0s * t1s;          /* i*z for every g */   \
                const float gf = gb1 ? u1s : u0s;                              \
                const float go = gb1 ? u0s : u1s;                              \
                cV = fmaf(gf, cV, prod);                                       \
                const float rr = frcp(1.0f + fex2(cV * (2.0f * L2E)));         \
                hOut = fmaf(-(go + go), rr, go);       /* go * tanh(c) */      \
            }
            SLOT_UPDATE(aA0, cA0, hA0v)
            SLOT_UPDATE(aB0, cB0, hB0v)
            SLOT_UPDATE(aA1, cA1, hA1v)
            SLOT_UPDATE(aB1, cB1, hB1v)
#undef SLOT_UPDATE

            if (g == 0) {
                sh_h[0][buf ^ 1][oA] = hA0v;
                sh_h[0][buf ^ 1][oB] = hB0v;
                sh_h[1][buf ^ 1][oA] = hA1v;
                sh_h[1][buf ^ 1][oB] = hB1v;
                oh0[0]  = hA0v;  oh0[32] = hB0v;
                oh1[0]  = hA1v;  oh1[32] = hB1v;
            } else if (g == 1) {
                oc0[0]  = cA0;   oc0[32] = cB0;
                oc1[0]  = cA1;   oc1[32] = cB1;
            }
            __syncthreads();   // the ONLY barrier per step (4 warps, both cells)

            buf ^= 1;
            oh0 += OROW;  oc0 += OROW;
            oh1 += OROW;  oc1 += OROW;
        }
#pragma unroll
        for (int j = 0; j < PF; ++j) {
            xA0[j] = yA0[j];  xB0[j] = yB0[j];
            xA1[j] = yA1[j];  xB1[j] = yB1[j];
        }
    }
}

extern "C" void kernel_launch(void* const* d_in, const int* in_sizes, int n_in,
                              void* d_out, int out_size)
{
    const float* Wx   = (const float*)d_in[0];  // [1024,16,12,64,4]
    const float* S0   = (const float*)d_in[1];  // [2,16,12,64]
    const float* R    = (const float*)d_in[2];  // [12,4,64,64]
    const float* bias = (const float*)d_in[3];  // [12,4,64]
    float* out = (float*)d_out;                 // [2,1025,16,12,64]

    flashrnn_lstm_kernel<<<NCELLS / 2, 128>>>(Wx, S0, R, bias, out);
}

// round 14
// speedup vs baseline: 1.1684x; 1.1684x over previous
#include <cuda_runtime.h>
#include <cstdint>

// Problem constants
#define T_STEPS 1024
#define BATCH   16
#define NHEADS  12
#define HD      64
#define NG      4
#define NCELLS  (BATCH * NHEADS)          // 192
#define CELLSTR (HD * NG)                 // 256 floats per (t,b,n)
#define TSTRIDE (NCELLS * CELLSTR)        // 49152 floats per timestep of Wx
#define OROW    ((size_t)NCELLS * HD)     // 12288 floats per timestep of out
#define PF      4                         // Wx prefetch distance (timesteps)

typedef unsigned long long ull;

__device__ __forceinline__ ull pk2(float lo, float hi) {
    ull r;
    asm("mov.b64 %0, {%1, %2};" : "=l"(r) : "r"(__float_as_uint(lo)), "r"(__float_as_uint(hi)));
    return r;
}
__device__ __forceinline__ void upk2(ull v, float& lo, float& hi) {
    unsigned a, b2;
    asm("mov.b64 {%0, %1}, %2;" : "=r"(a), "=r"(b2) : "l"(v));
    lo = __uint_as_float(a);
    hi = __uint_as_float(b2);
}
__device__ __forceinline__ void ffma2(ull& acc, ull a, ull b) {
    asm("fma.rn.f32x2 %0, %1, %2, %0;" : "+l"(acc) : "l"(a), "l"(b));
}
__device__ __forceinline__ ull fadd2(ull a, ull b) {
    ull r;
    asm("add.rn.f32x2 %0, %1, %2;" : "=l"(r) : "l"(a), "l"(b));
    return r;
}
__device__ __forceinline__ ull fmul2(ull a, ull b) {
    ull r;
    asm("mul.rn.f32x2 %0, %1, %2;" : "=l"(r) : "l"(a), "l"(b));
    return r;
}
__device__ __forceinline__ float frcp(float x) {
    float r;
    asm("rcp.approx.f32 %0, %1;" : "=f"(r) : "f"(x));
    return r;
}
__device__ __forceinline__ float fex2(float x) {
    float r;
    asm("ex2.approx.f32 %0, %1;" : "=f"(r) : "f"(x));
    return r;
}

// Scales folded into R/bias so the activation core is gate-uniform:
//   r = rcp(1 + ex2(s));  a = fma(k, r, m)
//   sigmoid (g in {0,1,3}): s = -log2(e)*x   -> a = r        (k=1,  m=0)
//   tanh    (g == 2):       s = 2*log2(e)*x  -> a = 1 - 2r   (k=-2, m=1)
#define L2E 1.4426950408889634f

__global__ void __launch_bounds__(128, 2)
flashrnn_lstm_kernel(const float* __restrict__ Wx,
                     const float* __restrict__ S0,
                     const float* __restrict__ R,
                     const float* __restrict__ bias,
                     float* __restrict__ out)
{
    const int cell = blockIdx.x;          // 0..191
    const int n = cell % NHEADS;
    const int b = cell / NHEADS;
    const int tid  = threadIdx.x;         // 0..127
    const int warp = tid >> 5;            // 0..3
    const int lane = tid & 31;
    const int g    = lane >> 3;           // gate 0..3 (i,f,z,o)
    const int ob   = lane & 7;            // output sub-index within gate group
    const int oA   = (warp << 3) | ob;    // first owned output (0..31)
    const int oB   = oA + 32;             // second owned output (32..63)

    // Source lanes for shfl.idx gate gather: gate q of output ob lives in lane (q<<3)|ob
    const int Li = ob;        // gate i
    const int Lf = ob | 8;    // gate f
    const int Lz = ob | 16;   // gate z
    const int Lo = ob | 24;   // gate o

    __shared__ __align__(16) float sh_h[2][HD];   // ping-pong hidden state

    // Per-gate activation constants (branch-free core)
    const float sg = (g == 2) ? (2.0f * L2E) : (-L2E);
    const float kg = (g == 2) ? -2.0f : 1.0f;
    const float mg = (g == 2) ?  1.0f : 0.0f;

    // ---- R rows for both slots, pre-scaled by sg, packed f32x2 ----
    // RpA[m]/RpB[m] multiply h elements (2m, 2m+1).
    ull RpA[32], RpB[32];
    {
        const ull sg2 = pk2(sg, sg);
        const float4* rA = reinterpret_cast<const float4*>(
            R + (((size_t)n * NG + g) * HD + oA) * HD);
        const float4* rB = reinterpret_cast<const float4*>(
            R + (((size_t)n * NG + g) * HD + oB) * HD);
#pragma unroll
        for (int k = 0; k < 16; ++k) {
            float4 vA = rA[k];
            float4 vB = rB[k];
            RpA[2 * k]     = fmul2(pk2(vA.x, vA.y), sg2);
            RpA[2 * k + 1] = fmul2(pk2(vA.z, vA.w), sg2);
            RpB[2 * k]     = fmul2(pk2(vB.x, vB.y), sg2);
            RpB[2 * k + 1] = fmul2(pk2(vB.z, vB.w), sg2);
        }
    }
    const float bvsA = bias[((size_t)n * NG + g) * HD + oA] * sg;
    const float bvsB = bias[((size_t)n * NG + g) * HD + oB] * sg;

    // ---- Initial states (c replicated x4 over g-lanes per output) ----
    const size_t bn = (size_t)b * NHEADS + n;
    const float h0A = S0[bn * HD + oA];
    const float h0B = S0[bn * HD + oB];
    float cA = S0[(size_t)NCELLS * HD + bn * HD + oA];
    float cB = S0[(size_t)NCELLS * HD + bn * HD + oB];

    float* out_h = out;                                 // [1025][192][64]
    float* out_c = out + (size_t)(T_STEPS + 1) * OROW;  // second state plane

    if (g == 0) {
        sh_h[0][oA] = h0A;
        sh_h[0][oB] = h0B;
        out_h[bn * HD + oA] = h0A;   // t=0 h
        out_h[bn * HD + oB] = h0B;
    } else if (g == 1) {
        out_c[bn * HD + oA] = cA;    // t=0 c
        out_c[bn * HD + oB] = cB;
    }

    // ---- Wx stream pointers (slot B is +32*NG floats from slot A) ----
    const float* wxA = Wx + bn * CELLSTR + (size_t)oA * NG + g;

    __syncthreads();

    float xcA[PF], xcB[PF];
#pragma unroll
    for (int j = 0; j < PF; ++j) {
        xcA[j] = __ldcs(wxA + (size_t)j * TSTRIDE);
        xcB[j] = __ldcs(wxA + (size_t)j * TSTRIDE + 32 * NG);
    }

    int buf = 0;
    float* oh = out_h + OROW + bn * HD + oA;   // t=1 row, slot A; slot B = +32
    float* oc = out_c + OROW + bn * HD + oA;

    // One recurrence step (identical math to the 415us champion; gather via shfl.idx)
#define STEP_BODY(XA, XB)                                                      \
    {                                                                          \
        const float xbA = fmaf((XA), sg, bvsA);                                \
        const float xbB = fmaf((XB), sg, bvsB);                                \
        ull accA[4], accB[4];                                                  \
        accA[0] = pk2(xbA, 0.0f);                                              \
        accB[0] = pk2(xbB, 0.0f);                                              \
        accA[1] = 0ULL; accA[2] = 0ULL; accA[3] = 0ULL;                        \
        accB[1] = 0ULL; accB[2] = 0ULL; accB[3] = 0ULL;                        \
        const ulonglong2* hb = reinterpret_cast<const ulonglong2*>(sh_h[buf]); \
        _Pragma("unroll")                                                      \
        for (int k = 0; k < 16; ++k) {                                         \
            ulonglong2 t2 = hb[k];                                             \
            ffma2(accA[(2 * k) & 3],     RpA[2 * k],     t2.x);                \
            ffma2(accA[(2 * k + 1) & 3], RpA[2 * k + 1], t2.y);                \
            ffma2(accB[(2 * k) & 3],     RpB[2 * k],     t2.x);                \
            ffma2(accB[(2 * k + 1) & 3], RpB[2 * k + 1], t2.y);                \
        }                                                                      \
        ull sa = fadd2(fadd2(accA[0], accA[1]), fadd2(accA[2], accA[3]));      \
        ull sb = fadd2(fadd2(accB[0], accB[1]), fadd2(accB[2], accB[3]));      \
        float lo, hi;                                                          \
        upk2(sa, lo, hi); const float sA = lo + hi;                            \
        upk2(sb, lo, hi); const float sB = lo + hi;                            \
        const float aA = fmaf(kg, frcp(1.0f + fex2(sA)), mg);                  \
        const float aB = fmaf(kg, frcp(1.0f + fex2(sB)), mg);                  \
        /* gate gather: direct indexed shuffles, no select network */          \
        const float giA = __shfl_sync(0xffffffffu, aA, Li);                    \
        const float gzA = __shfl_sync(0xffffffffu, aA, Lz);                    \
        const float gfA = __shfl_sync(0xffffffffu, aA, Lf);                    \
        const float goA = __shfl_sync(0xffffffffu, aA, Lo);                    \
        const float giB = __shfl_sync(0xffffffffu, aB, Li);                    \
        const float gzB = __shfl_sync(0xffffffffu, aB, Lz);                    \
        const float gfB = __shfl_sync(0xffffffffu, aB, Lf);                    \
        const float goB = __shfl_sync(0xffffffffu, aB, Lo);                    \
        cA = fmaf(gfA, cA, giA * gzA);                                         \
        cB = fmaf(gfB, cB, giB * gzB);                                         \
        const float rA2 = frcp(1.0f + fex2(cA * (2.0f * L2E)));                \
        const float rB2 = frcp(1.0f + fex2(cB * (2.0f * L2E)));                \
        const float hA = fmaf(-(goA + goA), rA2, goA);                         \
        const float hB = fmaf(-(goB + goB), rB2, goB);                         \
        if (g == 0) {                                                          \
            sh_h[buf ^ 1][oA] = hA;                                            \
            sh_h[buf ^ 1][oB] = hB;                                            \
            oh[0]  = hA;                                                       \
            oh[32] = hB;                                                       \
        } else if (g == 1) {                                                   \
            oc[0]  = cA;                                                       \
            oc[32] = cB;                                                       \
        }                                                                      \
        __syncthreads();                                                       \
        buf ^= 1;                                                              \
        oh += OROW;                                                            \
        oc += OROW;                                                            \
    }

    // ---- main loop: prefetch unconditional (no predication/selects) ----
    for (int t0 = 0; t0 < T_STEPS - PF; t0 += PF) {
        float xnA[PF], xnB[PF];
#pragma unroll
        for (int j = 0; j < PF; ++j) {
            const float* p = wxA + (size_t)(t0 + PF + j) * TSTRIDE;
            xnA[j] = __ldcs(p);
            xnB[j] = __ldcs(p + 32 * NG);
        }
#pragma unroll
        for (int j = 0; j < PF; ++j)
            STEP_BODY(xcA[j], xcB[j])
#pragma unroll
        for (int j = 0; j < PF; ++j) { xcA[j] = xnA[j]; xcB[j] = xnB[j]; }
    }
    // ---- tail: last PF steps, no prefetch ----
#pragma unroll
    for (int j = 0; j < PF; ++j)
        STEP_BODY(xcA[j], xcB[j])

#undef STEP_BODY
}

extern "C" void kernel_launch(void* const* d_in, const int* in_sizes, int n_in,
                              void* d_out, int out_size)
{
    const float* Wx   = (const float*)d_in[0];  // [1024,16,12,64,4]
    const float* S0   = (const float*)d_in[1];  // [2,16,12,64]
    const float* R    = (const float*)d_in[2];  // [12,4,64,64]
    const float* bias = (const float*)d_in[3];  // [12,4,64]
    float* out = (float*)d_out;                 // [2,1025,16,12,64]

    flashrnn_lstm_kernel<<<NCELLS, 128>>>(Wx, S0, R, bias, out);
}